// round 4
// baseline (speedup 1.0000x reference)
#include <cuda_runtime.h>
#include <cstddef>

#define C_IN 128
#define C_OUT 64
#define KOFF 27
#define TM 128           // pairs per tile
#define PAD 132          // padded row length of transposed A tile (multiple of 4, avoids bank conflicts)
#define CONV_THREADS 256

// scratch for BN statistics: [0..63] = sum, [64..127] = sumsq
__device__ float g_stats[2 * C_OUT];

// ---------------------------------------------------------------------------
// Kernel 0: zero the output accumulator + stats scratch
// ---------------------------------------------------------------------------
__global__ void __launch_bounds__(256) zero_kernel(float4* __restrict__ out4, int n4) {
    int i = blockIdx.x * 256 + threadIdx.x;
    float4 z = make_float4(0.f, 0.f, 0.f, 0.f);
    if (i < n4) out4[i] = z;
    if (blockIdx.x == 0 && threadIdx.x < 2 * C_OUT) g_stats[threadIdx.x] = 0.f;
}

// ---------------------------------------------------------------------------
// Kernel 1: gather - GEMM - scatter-add
// One block handles one (k, tile of TM pairs).
//   smem: At[C_IN][PAD]  (transposed gathered x tile)
//         Ws[C_IN][C_OUT] (weight[k])
// Each thread computes an 8x4 register tile of the TM x C_OUT output.
// ---------------------------------------------------------------------------
__global__ void __launch_bounds__(CONV_THREADS, 2) conv_kernel(
    const float* __restrict__ x, const float* __restrict__ w,
    const int* __restrict__ in_map, const int* __restrict__ out_map,
    float* __restrict__ out, int M, int tilesPerK)
{
    extern __shared__ float sm[];
    float* At = sm;                         // C_IN * PAD floats
    float* Ws = sm + C_IN * PAD;            // C_IN * C_OUT floats

    const int tid = threadIdx.x;
    const int k  = blockIdx.x / tilesPerK;
    const int m0 = (blockIdx.x % tilesPerK) * TM;

    // ---- load weight[k] into shared (broadcast-read later, no swizzle needed)
    {
        const float4* wk = (const float4*)(w + (size_t)k * C_IN * C_OUT);
        float4* Ws4 = (float4*)Ws;
        #pragma unroll
        for (int i = 0; i < 8; i++) Ws4[tid + i * 256] = wk[tid + i * 256];
    }

    // ---- gather x rows into transposed smem tile
    {
        const int p = tid & (TM - 1);   // pair within tile
        const int h = tid >> 7;         // channel half (0 or 1)
        const int m = m0 + p;
        if (m < M) {
            const int src = in_map[(size_t)k * M + m];
            const float4* xr = (const float4*)(x + (size_t)src * C_IN + h * 64);
            #pragma unroll
            for (int i = 0; i < 16; i++) {
                float4 v = xr[i];
                int kk = h * 64 + i * 4;
                At[(kk + 0) * PAD + p] = v.x;
                At[(kk + 1) * PAD + p] = v.y;
                At[(kk + 2) * PAD + p] = v.z;
                At[(kk + 3) * PAD + p] = v.w;
            }
        } else {
            #pragma unroll
            for (int i = 0; i < 16; i++) {
                int kk = h * 64 + i * 4;
                At[(kk + 0) * PAD + p] = 0.f;
                At[(kk + 1) * PAD + p] = 0.f;
                At[(kk + 2) * PAD + p] = 0.f;
                At[(kk + 3) * PAD + p] = 0.f;
            }
        }
    }
    __syncthreads();

    // ---- register-tiled GEMM: rows tr*8..tr*8+7, cols tc*4..tc*4+3
    const int tr = tid & 15;
    const int tc = tid >> 4;
    const float* Ap = At + tr * 8;
    const float* Bp = Ws + tc * 4;

    float acc[8][4];
    #pragma unroll
    for (int r = 0; r < 8; r++)
        #pragma unroll
        for (int c = 0; c < 4; c++) acc[r][c] = 0.f;

    #pragma unroll 4
    for (int kk = 0; kk < C_IN; kk++) {
        float4 b  = *(const float4*)(Bp + kk * C_OUT);
        float4 a0 = *(const float4*)(Ap + kk * PAD);
        float4 a1 = *(const float4*)(Ap + kk * PAD + 4);
        float av[8] = {a0.x, a0.y, a0.z, a0.w, a1.x, a1.y, a1.z, a1.w};
        float bv[4] = {b.x, b.y, b.z, b.w};
        #pragma unroll
        for (int r = 0; r < 8; r++)
            #pragma unroll
            for (int c = 0; c < 4; c++)
                acc[r][c] = fmaf(av[r], bv[c], acc[r][c]);
    }

    // ---- scatter-add with vectorized global reductions (16B per op)
    #pragma unroll
    for (int r = 0; r < 8; r++) {
        const int m2 = m0 + tr * 8 + r;
        if (m2 < M) {
            const int dst = out_map[(size_t)k * M + m2];
            float* op = out + (size_t)dst * C_OUT + tc * 4;
            asm volatile("red.global.add.v4.f32 [%0], {%1,%2,%3,%4};"
                         :: "l"(op), "f"(acc[r][0]), "f"(acc[r][1]),
                            "f"(acc[r][2]), "f"(acc[r][3])
                         : "memory");
        }
    }
}

// ---------------------------------------------------------------------------
// Kernel 2: per-channel sum / sumsq (training-mode BN statistics)
// ---------------------------------------------------------------------------
__global__ void __launch_bounds__(256) stats_kernel(const float* __restrict__ out, int nrows) {
    __shared__ float ssum[256];
    __shared__ float ssq[256];
    const int tid = threadIdx.x;
    const int c = tid & 63;
    const int r0 = blockIdx.x * 4 + (tid >> 6);
    const int rstride = gridDim.x * 4;

    float s = 0.f, q = 0.f;
    for (int r = r0; r < nrows; r += rstride) {
        float v = out[(size_t)r * C_OUT + c];
        s += v;
        q += v * v;
    }
    ssum[tid] = s;
    ssq[tid]  = q;
    __syncthreads();
    if (tid < 64) {
        s = ssum[tid] + ssum[tid + 64] + ssum[tid + 128] + ssum[tid + 192];
        q = ssq[tid]  + ssq[tid + 64]  + ssq[tid + 128]  + ssq[tid + 192];
        atomicAdd(&g_stats[c], s);
        atomicAdd(&g_stats[64 + c], q);
    }
}

// ---------------------------------------------------------------------------
// Kernel 3: normalize + affine + ReLU, in place.
// blockDim=256 -> grid stride is a multiple of 16 float4s, so each thread's
// channel quadruple is loop invariant.
// ---------------------------------------------------------------------------
__global__ void __launch_bounds__(256) norm_kernel(
    float* __restrict__ out, const float* __restrict__ gamma,
    const float* __restrict__ beta, int n4, float inv_n)
{
    const int c0 = (threadIdx.x * 4) & 63;
    float mean[4], scale[4], bias[4];
    #pragma unroll
    for (int j = 0; j < 4; j++) {
        int c = c0 + j;
        float m = g_stats[c] * inv_n;
        float var = g_stats[64 + c] * inv_n - m * m;
        float sc = gamma[c] * rsqrtf(var + 1e-5f);
        mean[j] = m;
        scale[j] = sc;
        bias[j] = beta[c];
    }

    float4* out4 = (float4*)out;
    const int stride = gridDim.x * blockDim.x;
    for (int i = blockIdx.x * blockDim.x + threadIdx.x; i < n4; i += stride) {
        float4 v = out4[i];
        v.x = fmaxf((v.x - mean[0]) * scale[0] + bias[0], 0.f);
        v.y = fmaxf((v.y - mean[1]) * scale[1] + bias[1], 0.f);
        v.z = fmaxf((v.z - mean[2]) * scale[2] + bias[2], 0.f);
        v.w = fmaxf((v.w - mean[3]) * scale[3] + bias[3], 0.f);
        out4[i] = v;
    }
}

// ---------------------------------------------------------------------------
// Launcher
// ---------------------------------------------------------------------------
extern "C" void kernel_launch(void* const* d_in, const int* in_sizes, int n_in,
                              void* d_out, int out_size)
{
    (void)n_in;
    const float* x      = (const float*)d_in[0];
    const float* w      = (const float*)d_in[1];
    const float* gamma  = (const float*)d_in[2];
    const float* beta   = (const float*)d_in[3];
    const int*   in_map = (const int*)d_in[4];
    const int*   out_map= (const int*)d_in[5];
    float* out = (float*)d_out;

    const int M = in_sizes[4] / KOFF;            // 100000
    const int nrows = out_size / C_OUT;          // 200000
    const int n4 = out_size / 4;

    const size_t smem = (size_t)(C_IN * PAD + C_IN * C_OUT) * sizeof(float); // 100352 B
    cudaFuncSetAttribute(conv_kernel, cudaFuncAttributeMaxDynamicSharedMemorySize, (int)smem);

    zero_kernel<<<(n4 + 255) / 256, 256>>>((float4*)out, n4);

    const int tilesPerK = (M + TM - 1) / TM;
    conv_kernel<<<KOFF * tilesPerK, CONV_THREADS, smem>>>(x, w, in_map, out_map, out, M, tilesPerK);

    stats_kernel<<<512, 256>>>(out, nrows);

    norm_kernel<<<2048, 256>>>(out, gamma, beta, n4, 1.0f / (float)nrows);
}

// round 6
// speedup vs baseline: 2.3361x; 2.3361x over previous
#include <cuda_runtime.h>
#include <cstddef>

#define C_IN 128
#define C_OUT 64
#define KOFF 27
#define TM 128           // pairs per tile
#define PAD 132          // padded row length of transposed A tile
#define CONV_THREADS 256

// scratch for BN statistics: [0..63] = sum, [64..127] = sumsq
__device__ float g_stats[2 * C_OUT];

// ---------------------------------------------------------------------------
// Kernel 0: zero the output accumulator + stats scratch
// ---------------------------------------------------------------------------
__global__ void __launch_bounds__(256) zero_kernel(float4* __restrict__ out4, int n4) {
    int i = blockIdx.x * 256 + threadIdx.x;
    float4 z = make_float4(0.f, 0.f, 0.f, 0.f);
    if (i < n4) out4[i] = z;
    if (blockIdx.x == 0 && threadIdx.x < 2 * C_OUT) g_stats[threadIdx.x] = 0.f;
}

// ---------------------------------------------------------------------------
// Kernel 1: gather - GEMM - scatter-add
// One block handles one (k, tile of TM pairs).
//   smem: At[C_IN][PAD]  (transposed gathered x tile)
//         Ws[C_IN][C_OUT] (weight[k])
// Thread mapping (bank-conflict-free):
//   tr = tid >> 4  (16 row groups of 8)  -> A loads are half-warp BROADCAST
//   tc = tid & 15  (16 col groups of 4)  -> B loads span all 32 banks/phase
// ---------------------------------------------------------------------------
__global__ void __launch_bounds__(CONV_THREADS, 2) conv_kernel(
    const float* __restrict__ x, const float* __restrict__ w,
    const int* __restrict__ in_map, const int* __restrict__ out_map,
    float* __restrict__ out, int M, int tilesPerK)
{
    extern __shared__ float sm[];
    float* At = sm;                         // C_IN * PAD floats
    float* Ws = sm + C_IN * PAD;            // C_IN * C_OUT floats

    const int tid = threadIdx.x;
    const int k  = blockIdx.x / tilesPerK;
    const int m0 = (blockIdx.x % tilesPerK) * TM;

    // ---- load weight[k] into shared
    {
        const float4* wk = (const float4*)(w + (size_t)k * C_IN * C_OUT);
        float4* Ws4 = (float4*)Ws;
        #pragma unroll
        for (int i = 0; i < 8; i++) Ws4[tid + i * 256] = wk[tid + i * 256];
    }

    // ---- gather x rows into transposed smem tile
    {
        const int p = tid & (TM - 1);   // pair within tile
        const int h = tid >> 7;         // channel half (0 or 1)
        const int m = m0 + p;
        if (m < M) {
            const int src = in_map[(size_t)k * M + m];
            const float4* xr = (const float4*)(x + (size_t)src * C_IN + h * 64);
            #pragma unroll
            for (int i = 0; i < 16; i++) {
                float4 v = xr[i];
                int kk = h * 64 + i * 4;
                At[(kk + 0) * PAD + p] = v.x;
                At[(kk + 1) * PAD + p] = v.y;
                At[(kk + 2) * PAD + p] = v.z;
                At[(kk + 3) * PAD + p] = v.w;
            }
        } else {
            #pragma unroll
            for (int i = 0; i < 16; i++) {
                int kk = h * 64 + i * 4;
                At[(kk + 0) * PAD + p] = 0.f;
                At[(kk + 1) * PAD + p] = 0.f;
                At[(kk + 2) * PAD + p] = 0.f;
                At[(kk + 3) * PAD + p] = 0.f;
            }
        }
    }

    // ---- preload scatter indices (hide LDG latency under the GEMM)
    const int tr = tid >> 4;          // row group  (broadcast A within half-warp)
    const int tc = tid & 15;          // col group  (conflict-free B)
    int dst[8];
    int mrow[8];
    #pragma unroll
    for (int r = 0; r < 8; r++) {
        mrow[r] = m0 + tr * 8 + r;
        dst[r] = (mrow[r] < M) ? out_map[(size_t)k * M + mrow[r]] : -1;
    }

    __syncthreads();

    // ---- register-tiled GEMM: rows tr*8..tr*8+7, cols tc*4..tc*4+3
    const float* Ap = At + tr * 8;
    const float* Bp = Ws + tc * 4;

    float acc[8][4];
    #pragma unroll
    for (int r = 0; r < 8; r++)
        #pragma unroll
        for (int c = 0; c < 4; c++) acc[r][c] = 0.f;

    #pragma unroll 4
    for (int kk = 0; kk < C_IN; kk++) {
        float4 b  = *(const float4*)(Bp + kk * C_OUT);
        float4 a0 = *(const float4*)(Ap + kk * PAD);
        float4 a1 = *(const float4*)(Ap + kk * PAD + 4);
        float av[8] = {a0.x, a0.y, a0.z, a0.w, a1.x, a1.y, a1.z, a1.w};
        float bv[4] = {b.x, b.y, b.z, b.w};
        #pragma unroll
        for (int r = 0; r < 8; r++)
            #pragma unroll
            for (int c = 0; c < 4; c++)
                acc[r][c] = fmaf(av[r], bv[c], acc[r][c]);
    }

    // ---- scatter-add with vectorized global reductions (16B per op)
    #pragma unroll
    for (int r = 0; r < 8; r++) {
        if (dst[r] >= 0) {
            float* op = out + (size_t)dst[r] * C_OUT + tc * 4;
            asm volatile("red.global.add.v4.f32 [%0], {%1,%2,%3,%4};"
                         :: "l"(op), "f"(acc[r][0]), "f"(acc[r][1]),
                            "f"(acc[r][2]), "f"(acc[r][3])
                         : "memory");
        }
    }
}

// ---------------------------------------------------------------------------
// Kernel 2: per-channel sum / sumsq (training-mode BN statistics)
// ---------------------------------------------------------------------------
__global__ void __launch_bounds__(256) stats_kernel(const float* __restrict__ out, int nrows) {
    __shared__ float ssum[256];
    __shared__ float ssq[256];
    const int tid = threadIdx.x;
    const int c = tid & 63;
    const int r0 = blockIdx.x * 4 + (tid >> 6);
    const int rstride = gridDim.x * 4;

    float s = 0.f, q = 0.f;
    for (int r = r0; r < nrows; r += rstride) {
        float v = out[(size_t)r * C_OUT + c];
        s += v;
        q += v * v;
    }
    ssum[tid] = s;
    ssq[tid]  = q;
    __syncthreads();
    if (tid < 64) {
        s = ssum[tid] + ssum[tid + 64] + ssum[tid + 128] + ssum[tid + 192];
        q = ssq[tid]  + ssq[tid + 64]  + ssq[tid + 128]  + ssq[tid + 192];
        atomicAdd(&g_stats[c], s);
        atomicAdd(&g_stats[64 + c], q);
    }
}

// ---------------------------------------------------------------------------
// Kernel 3: normalize + affine + ReLU, in place.
// ---------------------------------------------------------------------------
__global__ void __launch_bounds__(256) norm_kernel(
    float* __restrict__ out, const float* __restrict__ gamma,
    const float* __restrict__ beta, int n4, float inv_n)
{
    const int c0 = (threadIdx.x * 4) & 63;
    float mean[4], scale[4], bias[4];
    #pragma unroll
    for (int j = 0; j < 4; j++) {
        int c = c0 + j;
        float m = g_stats[c] * inv_n;
        float var = g_stats[64 + c] * inv_n - m * m;
        float sc = gamma[c] * rsqrtf(var + 1e-5f);
        mean[j] = m;
        scale[j] = sc;
        bias[j] = beta[c];
    }

    float4* out4 = (float4*)out;
    const int stride = gridDim.x * blockDim.x;
    for (int i = blockIdx.x * blockDim.x + threadIdx.x; i < n4; i += stride) {
        float4 v = out4[i];
        v.x = fmaxf((v.x - mean[0]) * scale[0] + bias[0], 0.f);
        v.y = fmaxf((v.y - mean[1]) * scale[1] + bias[1], 0.f);
        v.z = fmaxf((v.z - mean[2]) * scale[2] + bias[2], 0.f);
        v.w = fmaxf((v.w - mean[3]) * scale[3] + bias[3], 0.f);
        out4[i] = v;
    }
}

// ---------------------------------------------------------------------------
// Launcher
// ---------------------------------------------------------------------------
extern "C" void kernel_launch(void* const* d_in, const int* in_sizes, int n_in,
                              void* d_out, int out_size)
{
    (void)n_in;
    const float* x      = (const float*)d_in[0];
    const float* w      = (const float*)d_in[1];
    const float* gamma  = (const float*)d_in[2];
    const float* beta   = (const float*)d_in[3];
    const int*   in_map = (const int*)d_in[4];
    const int*   out_map= (const int*)d_in[5];
    float* out = (float*)d_out;

    const int M = in_sizes[4] / KOFF;            // 100000
    const int nrows = out_size / C_OUT;          // 200000
    const int n4 = out_size / 4;

    const size_t smem = (size_t)(C_IN * PAD + C_IN * C_OUT) * sizeof(float); // 100352 B
    cudaFuncSetAttribute(conv_kernel, cudaFuncAttributeMaxDynamicSharedMemorySize, (int)smem);

    zero_kernel<<<(n4 + 255) / 256, 256>>>((float4*)out, n4);

    const int tilesPerK = (M + TM - 1) / TM;
    conv_kernel<<<KOFF * tilesPerK, CONV_THREADS, smem>>>(x, w, in_map, out_map, out, M, tilesPerK);

    stats_kernel<<<512, 256>>>(out, nrows);

    norm_kernel<<<2048, 256>>>(out, gamma, beta, n4, 1.0f / (float)nrows);
}

// round 8
// speedup vs baseline: 2.7301x; 1.1686x over previous
#include <cuda_runtime.h>
#include <cstddef>

#define C_IN 128
#define C_OUT 64
#define KOFF 27
#define TM 128           // pairs per tile
#define PAD 132          // padded row length of transposed A tile
#define CONV_THREADS 256

// scratch for BN statistics: [0..63] = sum, [64..127] = sumsq
__device__ float g_stats[2 * C_OUT];

// pack two f32 into a 64-bit register pair (lo, hi)
__device__ __forceinline__ unsigned long long pack2(float lo, float hi) {
    unsigned long long r;
    asm("mov.b64 %0, {%1, %2};" : "=l"(r) : "f"(lo), "f"(hi));
    return r;
}

// ---------------------------------------------------------------------------
// Kernel 0: zero the output accumulator + stats scratch
// ---------------------------------------------------------------------------
__global__ void __launch_bounds__(256) zero_kernel(float4* __restrict__ out4, int n4) {
    int i = blockIdx.x * 256 + threadIdx.x;
    float4 z = make_float4(0.f, 0.f, 0.f, 0.f);
    if (i < n4) out4[i] = z;
    if (blockIdx.x == 0 && threadIdx.x < 2 * C_OUT) g_stats[threadIdx.x] = 0.f;
}

// ---------------------------------------------------------------------------
// Kernel 1: gather - GEMM - scatter-add
// One block handles one (k, tile of TM pairs).
//   smem: At[C_IN][PAD]  (transposed gathered x tile)
//         Ws[C_IN][C_OUT] (weight[k])
// Thread mapping (bank-conflict-free):
//   tr = tid >> 4  (16 row groups of 8)  -> A loads are half-warp BROADCAST
//   tc = tid & 15  (16 col groups of 4)  -> B loads span all 32 banks/phase
// GEMM inner loop uses packed fma.rn.f32x2 (FFMA2): row pairs (2p, 2p+1)
// live in one 64-bit lane pair straight out of the LDS.128 A load.
// ---------------------------------------------------------------------------
__global__ void __launch_bounds__(CONV_THREADS, 2) conv_kernel(
    const float* __restrict__ x, const float* __restrict__ w,
    const int* __restrict__ in_map, const int* __restrict__ out_map,
    float* __restrict__ out, int M, int tilesPerK)
{
    extern __shared__ float sm[];
    float* At = sm;                         // C_IN * PAD floats
    float* Ws = sm + C_IN * PAD;            // C_IN * C_OUT floats

    const int tid = threadIdx.x;
    const int k  = blockIdx.x / tilesPerK;
    const int m0 = (blockIdx.x % tilesPerK) * TM;

    // ---- load weight[k] into shared
    {
        const float4* wk = (const float4*)(w + (size_t)k * C_IN * C_OUT);
        float4* Ws4 = (float4*)Ws;
        #pragma unroll
        for (int i = 0; i < 8; i++) Ws4[tid + i * 256] = wk[tid + i * 256];
    }

    // ---- gather x rows into transposed smem tile
    {
        const int p = tid & (TM - 1);   // pair within tile
        const int h = tid >> 7;         // channel half (0 or 1)
        const int m = m0 + p;
        if (m < M) {
            const int src = in_map[(size_t)k * M + m];
            const float4* xr = (const float4*)(x + (size_t)src * C_IN + h * 64);
            #pragma unroll
            for (int i = 0; i < 16; i++) {
                float4 v = xr[i];
                int kk = h * 64 + i * 4;
                At[(kk + 0) * PAD + p] = v.x;
                At[(kk + 1) * PAD + p] = v.y;
                At[(kk + 2) * PAD + p] = v.z;
                At[(kk + 3) * PAD + p] = v.w;
            }
        } else {
            #pragma unroll
            for (int i = 0; i < 16; i++) {
                int kk = h * 64 + i * 4;
                At[(kk + 0) * PAD + p] = 0.f;
                At[(kk + 1) * PAD + p] = 0.f;
                At[(kk + 2) * PAD + p] = 0.f;
                At[(kk + 3) * PAD + p] = 0.f;
            }
        }
    }

    // ---- preload scatter indices (hide LDG latency under the GEMM)
    const int tr = tid >> 4;          // row group  (broadcast A within half-warp)
    const int tc = tid & 15;          // col group  (conflict-free B)
    int dst[8];
    #pragma unroll
    for (int r = 0; r < 8; r++) {
        const int m2 = m0 + tr * 8 + r;
        dst[r] = (m2 < M) ? out_map[(size_t)k * M + m2] : -1;
    }

    __syncthreads();

    // ---- register-tiled GEMM with packed FFMA2
    // accP[p][c] holds rows (2p, 2p+1), column tc*4+c, packed {lo=row 2p, hi=row 2p+1}
    const float* Ap = At + tr * 8;
    const float* Bp = Ws + tc * 4;

    unsigned long long accP[4][4];
    #pragma unroll
    for (int p = 0; p < 4; p++)
        #pragma unroll
        for (int c = 0; c < 4; c++) accP[p][c] = 0ull;

    #pragma unroll 4
    for (int kk = 0; kk < C_IN; kk++) {
        float4 b = *(const float4*)(Bp + kk * C_OUT);
        // A rows 0..3 and 4..7, already paired as 64-bit lanes
        ulonglong2 aLo = *(const ulonglong2*)(Ap + kk * PAD);       // {r0r1, r2r3}
        ulonglong2 aHi = *(const ulonglong2*)(Ap + kk * PAD + 4);   // {r4r5, r6r7}
        unsigned long long av[4] = {aLo.x, aLo.y, aHi.x, aHi.y};
        unsigned long long bb[4] = {pack2(b.x, b.x), pack2(b.y, b.y),
                                    pack2(b.z, b.z), pack2(b.w, b.w)};
        #pragma unroll
        for (int p = 0; p < 4; p++)
            #pragma unroll
            for (int c = 0; c < 4; c++)
                asm("fma.rn.f32x2 %0, %1, %2, %0;"
                    : "+l"(accP[p][c]) : "l"(av[p]), "l"(bb[c]));
    }

    // ---- unpack and scatter-add with vectorized global reductions
    #pragma unroll
    for (int p = 0; p < 4; p++) {
        float lo[4], hi[4];
        #pragma unroll
        for (int c = 0; c < 4; c++)
            asm("mov.b64 {%0, %1}, %2;" : "=f"(lo[c]), "=f"(hi[c]) : "l"(accP[p][c]));
        if (dst[2 * p] >= 0) {
            float* op = out + (size_t)dst[2 * p] * C_OUT + tc * 4;
            asm volatile("red.global.add.v4.f32 [%0], {%1,%2,%3,%4};"
                         :: "l"(op), "f"(lo[0]), "f"(lo[1]), "f"(lo[2]), "f"(lo[3])
                         : "memory");
        }
        if (dst[2 * p + 1] >= 0) {
            float* op = out + (size_t)dst[2 * p + 1] * C_OUT + tc * 4;
            asm volatile("red.global.add.v4.f32 [%0], {%1,%2,%3,%4};"
                         :: "l"(op), "f"(hi[0]), "f"(hi[1]), "f"(hi[2]), "f"(hi[3])
                         : "memory");
        }
    }
}

// ---------------------------------------------------------------------------
// Kernel 2: per-channel sum / sumsq (training-mode BN statistics)
// ---------------------------------------------------------------------------
__global__ void __launch_bounds__(256) stats_kernel(const float* __restrict__ out, int nrows) {
    __shared__ float ssum[256];
    __shared__ float ssq[256];
    const int tid = threadIdx.x;
    const int c = tid & 63;
    const int r0 = blockIdx.x * 4 + (tid >> 6);
    const int rstride = gridDim.x * 4;

    float s = 0.f, q = 0.f;
    for (int r = r0; r < nrows; r += rstride) {
        float v = out[(size_t)r * C_OUT + c];
        s += v;
        q += v * v;
    }
    ssum[tid] = s;
    ssq[tid]  = q;
    __syncthreads();
    if (tid < 64) {
        s = ssum[tid] + ssum[tid + 64] + ssum[tid + 128] + ssum[tid + 192];
        q = ssq[tid]  + ssq[tid + 64]  + ssq[tid + 128]  + ssq[tid + 192];
        atomicAdd(&g_stats[c], s);
        atomicAdd(&g_stats[64 + c], q);
    }
}

// ---------------------------------------------------------------------------
// Kernel 3: normalize + affine + ReLU, in place.
// ---------------------------------------------------------------------------
__global__ void __launch_bounds__(256) norm_kernel(
    float* __restrict__ out, const float* __restrict__ gamma,
    const float* __restrict__ beta, int n4, float inv_n)
{
    const int c0 = (threadIdx.x * 4) & 63;
    float mean[4], scale[4], bias[4];
    #pragma unroll
    for (int j = 0; j < 4; j++) {
        int c = c0 + j;
        float m = g_stats[c] * inv_n;
        float var = g_stats[64 + c] * inv_n - m * m;
        float sc = gamma[c] * rsqrtf(var + 1e-5f);
        mean[j] = m;
        scale[j] = sc;
        bias[j] = beta[c];
    }

    float4* out4 = (float4*)out;
    const int stride = gridDim.x * blockDim.x;
    for (int i = blockIdx.x * blockDim.x + threadIdx.x; i < n4; i += stride) {
        float4 v = out4[i];
        v.x = fmaxf((v.x - mean[0]) * scale[0] + bias[0], 0.f);
        v.y = fmaxf((v.y - mean[1]) * scale[1] + bias[1], 0.f);
        v.z = fmaxf((v.z - mean[2]) * scale[2] + bias[2], 0.f);
        v.w = fmaxf((v.w - mean[3]) * scale[3] + bias[3], 0.f);
        out4[i] = v;
    }
}

// ---------------------------------------------------------------------------
// Launcher
// ---------------------------------------------------------------------------
extern "C" void kernel_launch(void* const* d_in, const int* in_sizes, int n_in,
                              void* d_out, int out_size)
{
    (void)n_in;
    const float* x      = (const float*)d_in[0];
    const float* w      = (const float*)d_in[1];
    const float* gamma  = (const float*)d_in[2];
    const float* beta   = (const float*)d_in[3];
    const int*   in_map = (const int*)d_in[4];
    const int*   out_map= (const int*)d_in[5];
    float* out = (float*)d_out;

    const int M = in_sizes[4] / KOFF;            // 100000
    const int nrows = out_size / C_OUT;          // 200000
    const int n4 = out_size / 4;

    const size_t smem = (size_t)(C_IN * PAD + C_IN * C_OUT) * sizeof(float); // 100352 B
    cudaFuncSetAttribute(conv_kernel, cudaFuncAttributeMaxDynamicSharedMemorySize, (int)smem);

    zero_kernel<<<(n4 + 255) / 256, 256>>>((float4*)out, n4);

    const int tilesPerK = (M + TM - 1) / TM;
    conv_kernel<<<KOFF * tilesPerK, CONV_THREADS, smem>>>(x, w, in_map, out_map, out, M, tilesPerK);

    stats_kernel<<<512, 256>>>(out, nrows);

    norm_kernel<<<2048, 256>>>(out, gamma, beta, n4, 1.0f / (float)nrows);
}